// round 1
// baseline (speedup 1.0000x reference)
#include <cuda_runtime.h>

// Problem constants (fixed shapes per setup_inputs)
#define NN 4096
#define BB 512
#define DTc 0.1f

// GEMM tiling
#define BM 128
#define BN 64
#define BK 16
#define TM 8
#define TN 4

// Scratch (device globals — no allocation allowed)
__device__ __align__(128) float g_P22[(size_t)NN * NN];      // 64 MB
__device__ __align__(128) float g_h[2][(size_t)NN * BB];     // 2 x 8 MB
__device__ __align__(128) float g_x[2][2 * BB];
__device__ __align__(128) float g_zpart[16 * BB];

// ---------------------------------------------------------------------------
// Build P22 = DT*(W + U V^T) + (1-DT) I + (C@Bmat) * M Z   (one pass, 128 MB traffic)
// ---------------------------------------------------------------------------
__global__ void build_p22_kernel(const float* __restrict__ W,
                                 const float* __restrict__ U,
                                 const float* __restrict__ V,
                                 const float* __restrict__ Mv,
                                 const float* __restrict__ Z,
                                 const float* __restrict__ Cc,
                                 const float* __restrict__ Bm) {
    int i  = blockIdx.y;
    int j4 = blockIdx.x * blockDim.x + threadIdx.x;   // 0..NN/4-1
    int j  = j4 * 4;
    float cb = Cc[0] * Bm[0] + Cc[1] * Bm[1];
    float mi = Mv[i];
    float u0 = U[i * 4 + 0], u1 = U[i * 4 + 1], u2 = U[i * 4 + 2], u3 = U[i * 4 + 3];
    float4 w = *(const float4*)(W + (size_t)i * NN + j);
    const float* wp = &w.x;
    float4 o;
    float* op = &o.x;
#pragma unroll
    for (int jj = 0; jj < 4; ++jj) {
        int jc = j + jj;
        float4 vv = *(const float4*)(V + (size_t)jc * 4);
        float uv = u0 * vv.x + u1 * vv.y + u2 * vv.z + u3 * vv.w;
        float val = DTc * (wp[jj] + uv) + cb * mi * Z[jc];
        if (jc == i) val += 1.0f - DTc;
        op[jj] = val;
    }
    *(float4*)(g_P22 + (size_t)i * NN + j) = o;
}

// ---------------------------------------------------------------------------
// Init state buffers
// ---------------------------------------------------------------------------
__global__ void init_h_kernel(const float* __restrict__ h0) {
    size_t idx = (size_t)blockIdx.x * blockDim.x + threadIdx.x;
    ((float4*)g_h[0])[idx] = ((const float4*)h0)[idx];
}

__global__ void init_x_kernel(const float* __restrict__ x0, const float* __restrict__ x1) {
    int b = threadIdx.x;
    g_x[0][b]      = x0[b];
    g_x[0][BB + b] = x1[b];
}

// ---------------------------------------------------------------------------
// Copy current h into traj (pre-update state)
// ---------------------------------------------------------------------------
__global__ void copy_h_out_kernel(float* __restrict__ dst, int p) {
    size_t idx = (size_t)blockIdx.x * blockDim.x + threadIdx.x;
    ((float4*)dst)[idx] = ((const float4*)g_h[p])[idx];
}

// ---------------------------------------------------------------------------
// Zh partial reduction: zpart[c][b] = sum_{j in chunk c} Z[j] * h[j][b]
// grid (BB/256, 16), block 256
// ---------------------------------------------------------------------------
__global__ void zh_partial_kernel(int p, const float* __restrict__ Z) {
    int b = blockIdx.x * blockDim.x + threadIdx.x;
    int c = blockIdx.y;
    const float* __restrict__ h = g_h[p];
    float s = 0.f;
    int j0 = c * 256;
#pragma unroll 8
    for (int j = j0; j < j0 + 256; ++j)
        s = fmaf(Z[j], h[(size_t)j * BB + b], s);
    g_zpart[c * BB + b] = s;
}

// ---------------------------------------------------------------------------
// Finish Zh, write con + traj x-rows, compute new x
// block: 512 threads, 1 block
// ---------------------------------------------------------------------------
__global__ void xupdate_kernel(int p, const float* __restrict__ Amat,
                               const float* __restrict__ Bm,
                               float* __restrict__ traj_x,
                               float* __restrict__ con) {
    int b = threadIdx.x;
    float zh = 0.f;
#pragma unroll
    for (int c = 0; c < 16; ++c) zh += g_zpart[c * BB + b];
    float x0 = g_x[p][b], x1 = g_x[p][BB + b];
    con[b]         = Bm[1] * zh;          // P_out row = Bmat[1,0] * Z
    traj_x[b]      = x0;
    traj_x[BB + b] = x1;
    int q = p ^ 1;
    g_x[q][b]      = Amat[0] * x0 + Amat[1] * x1 + Bm[0] * zh;
    g_x[q][BB + b] = Amat[2] * x0 + Amat[3] * x1 + Bm[1] * zh;
}

// ---------------------------------------------------------------------------
// h_{t+1} = P22 @ h_t + DT * M * (C@A @ x_t)
// Double-buffered smem tiled SGEMM: 128x64 tile, BK=16, 256 threads, 8x4/thread
// grid (BB/BN=8, NN/BM=32)
// ---------------------------------------------------------------------------
__global__ __launch_bounds__(256) void gemm_step_kernel(
    int p,
    const float* __restrict__ Mv,
    const float* __restrict__ Cc,
    const float* __restrict__ Amat) {
    const float* __restrict__ Ag  = g_P22;
    const float* __restrict__ Bg  = g_h[p];
    float* __restrict__ Cg        = g_h[p ^ 1];
    const float* __restrict__ xin = g_x[p];

    __shared__ float As[2][BK][BM];
    __shared__ float Bs[2][BK][BN];

    int tid = threadIdx.x;
    int ty = tid >> 4;          // 0..15
    int tx = tid & 15;          // 0..15
    int rowBase = blockIdx.y * BM;
    int colBase = blockIdx.x * BN;

    // A load mapping: thread loads rows ar0 and ar0+64, 4 consecutive k's at ac
    int ar0 = tid >> 2;
    int ac  = (tid & 3) * 4;
    // B load mapping: row br (k), 4 consecutive cols at bc
    int br = tid >> 4;
    int bc = (tid & 15) * 4;

    const float* Aptr = Ag + (size_t)rowBase * NN;
    const float* Bptr = Bg + colBase;

    // prologue: stage tile k0=0 into buffer 0
    float4 pa0 = *(const float4*)(Aptr + (size_t)ar0 * NN + ac);
    float4 pa1 = *(const float4*)(Aptr + (size_t)(ar0 + 64) * NN + ac);
    float4 pb  = *(const float4*)(Bptr + (size_t)br * BB + bc);

    As[0][ac + 0][ar0] = pa0.x; As[0][ac + 1][ar0] = pa0.y;
    As[0][ac + 2][ar0] = pa0.z; As[0][ac + 3][ar0] = pa0.w;
    As[0][ac + 0][ar0 + 64] = pa1.x; As[0][ac + 1][ar0 + 64] = pa1.y;
    As[0][ac + 2][ar0 + 64] = pa1.z; As[0][ac + 3][ar0 + 64] = pa1.w;
    *(float4*)&Bs[0][br][bc] = pb;
    __syncthreads();

    float acc[TM][TN];
#pragma unroll
    for (int i = 0; i < TM; ++i)
#pragma unroll
        for (int j = 0; j < TN; ++j) acc[i][j] = 0.f;

    int buf = 0;
    for (int k0 = 0; k0 < NN; k0 += BK) {
        int nk = k0 + BK;
        if (nk < NN) {
            pa0 = *(const float4*)(Aptr + (size_t)ar0 * NN + nk + ac);
            pa1 = *(const float4*)(Aptr + (size_t)(ar0 + 64) * NN + nk + ac);
            pb  = *(const float4*)(Bptr + (size_t)(nk + br) * BB + bc);
        }
#pragma unroll
        for (int k = 0; k < BK; ++k) {
            float4 a0 = *(const float4*)&As[buf][k][ty * TM];
            float4 a1 = *(const float4*)&As[buf][k][ty * TM + 4];
            float4 b0 = *(const float4*)&Bs[buf][k][tx * TN];
            const float ra[TM] = {a0.x, a0.y, a0.z, a0.w, a1.x, a1.y, a1.z, a1.w};
            const float rb[TN] = {b0.x, b0.y, b0.z, b0.w};
#pragma unroll
            for (int i = 0; i < TM; ++i)
#pragma unroll
                for (int j = 0; j < TN; ++j)
                    acc[i][j] = fmaf(ra[i], rb[j], acc[i][j]);
        }
        if (nk < NN) {
            int nb = buf ^ 1;
            As[nb][ac + 0][ar0] = pa0.x; As[nb][ac + 1][ar0] = pa0.y;
            As[nb][ac + 2][ar0] = pa0.z; As[nb][ac + 3][ar0] = pa0.w;
            As[nb][ac + 0][ar0 + 64] = pa1.x; As[nb][ac + 1][ar0 + 64] = pa1.y;
            As[nb][ac + 2][ar0 + 64] = pa1.z; As[nb][ac + 3][ar0 + 64] = pa1.w;
            *(float4*)&Bs[nb][br][bc] = pb;
            __syncthreads();
            buf = nb;
        }
    }

    // Epilogue: add rank-2 P21 @ x term: DT * M[i] * (CA0*x0[b] + CA1*x1[b])
    float CA0 = Cc[0] * Amat[0] + Cc[1] * Amat[2];
    float CA1 = Cc[0] * Amat[1] + Cc[1] * Amat[3];
    float e[TN];
#pragma unroll
    for (int j = 0; j < TN; ++j) {
        int b = colBase + tx * TN + j;
        e[j] = CA0 * xin[b] + CA1 * xin[BB + b];
    }
#pragma unroll
    for (int i = 0; i < TM; ++i) {
        int row = rowBase + ty * TM + i;
        float m = DTc * Mv[row];
        float4 o;
        o.x = acc[i][0] + m * e[0];
        o.y = acc[i][1] + m * e[1];
        o.z = acc[i][2] + m * e[2];
        o.w = acc[i][3] + m * e[3];
        *(float4*)&Cg[(size_t)row * BB + colBase + tx * TN] = o;
    }
}

// ---------------------------------------------------------------------------
extern "C" void kernel_launch(void* const* d_in, const int* in_sizes, int n_in,
                              void* d_out, int out_size) {
    const float* x0 = (const float*)d_in[0];
    const float* x1 = (const float*)d_in[1];
    const float* h0 = (const float*)d_in[2];
    const float* A  = (const float*)d_in[3];
    const float* Bm = (const float*)d_in[4];
    const float* C  = (const float*)d_in[5];
    const float* Mv = (const float*)d_in[6];
    const float* Z  = (const float*)d_in[7];
    const float* U  = (const float*)d_in[8];
    const float* V  = (const float*)d_in[9];
    const float* W  = (const float*)d_in[10];
    // d_in[11] = num_steps (device scalar) — derive steps from out_size instead.

    long long per_step_full = (long long)BB * (NN + 2 + 1);   // traj row-block + con
    int steps = (int)((long long)out_size / per_step_full);
    if ((long long)steps * per_step_full != (long long)out_size) {
        // fallback: output is traj only
        steps = (int)((long long)out_size / ((long long)BB * (NN + 2)));
    }

    float* out  = (float*)d_out;
    float* traj = out;
    float* con  = out + (size_t)steps * (NN + 2) * BB;

    build_p22_kernel<<<dim3(NN / 4 / 256, NN), 256>>>(W, U, V, Mv, Z, C, Bm);
    init_h_kernel<<<(NN * BB / 4) / 256, 256>>>(h0);
    init_x_kernel<<<1, BB>>>(x0, x1);

    for (int t = 0; t < steps; ++t) {
        int p = t & 1;
        float* traj_t = traj + (size_t)t * (NN + 2) * BB;
        copy_h_out_kernel<<<(NN * BB / 4) / 256, 256>>>(traj_t + 2 * BB, p);
        zh_partial_kernel<<<dim3(BB / 256, 16), 256>>>(p, Z);
        xupdate_kernel<<<1, BB>>>(p, A, Bm, traj_t, con + (size_t)t * BB);
        gemm_step_kernel<<<dim3(BB / BN, NN / BM), 256>>>(p, Mv, C, A);
    }
}

// round 3
// speedup vs baseline: 2.2880x; 2.2880x over previous
#include <cuda_runtime.h>
#include <cuda_bf16.h>
#include <cstdint>

#define NN 4096
#define BB 512
#define DTc 0.1f

// GEMM tiling (mma.sync bf16)
#define BM 128
#define BN 128
#define BKt 32
#define NKT (NN / BKt)        // 128 k-tile iterations
#define ROWB 80               // padded smem row bytes (64B data + 16B pad)
#define TILEB (128 * ROWB)    // 10240 bytes per operand tile
#define STAGEB (4 * TILEB)    // Ahi, Alo, Bhi, Blo
#define NSTG 3
#define SMEM_BYTES (NSTG * STAGEB)   // 122880

// --------------------------------------------------------------------------
// Device scratch (no allocation allowed)
// --------------------------------------------------------------------------
__device__ __align__(256) __nv_bfloat16 g_Ahi[(size_t)NN * NN];    // 32 MB
__device__ __align__(256) __nv_bfloat16 g_Alo[(size_t)NN * NN];    // 32 MB
__device__ __align__(256) __nv_bfloat16 g_Bhi[2][(size_t)BB * NN]; // 2x4 MB
__device__ __align__(256) __nv_bfloat16 g_Blo[2][(size_t)BB * NN]; // 2x4 MB
__device__ __align__(256) float g_hT[2][(size_t)BB * NN];          // 2x8 MB
__device__ float g_x[2][2 * BB];
__device__ float g_zh[BB];

// --------------------------------------------------------------------------
// Helpers
// --------------------------------------------------------------------------
__device__ __forceinline__ uint32_t smem_u32(const void* p) {
    return (uint32_t)__cvta_generic_to_shared((void*)p);
}

__device__ __forceinline__ void cp16(uint32_t dst, const void* src) {
    asm volatile("cp.async.cg.shared.global [%0], [%1], 16;" :: "r"(dst), "l"(src) : "memory");
}

__device__ __forceinline__ void ldsm4(uint32_t* r, uint32_t a) {
    asm volatile("ldmatrix.sync.aligned.m8n8.x4.shared.b16 {%0,%1,%2,%3}, [%4];"
                 : "=r"(r[0]), "=r"(r[1]), "=r"(r[2]), "=r"(r[3]) : "r"(a));
}

__device__ __forceinline__ void ldsm2(uint32_t* r, uint32_t a) {
    asm volatile("ldmatrix.sync.aligned.m8n8.x2.shared.b16 {%0,%1}, [%2];"
                 : "=r"(r[0]), "=r"(r[1]) : "r"(a));
}

__device__ __forceinline__ void mma_bf16(float* d, const uint32_t* a, const uint32_t* b) {
    asm volatile("mma.sync.aligned.m16n8k16.row.col.f32.bf16.bf16.f32 "
                 "{%0,%1,%2,%3}, {%4,%5,%6,%7}, {%8,%9}, {%0,%1,%2,%3};"
                 : "+f"(d[0]), "+f"(d[1]), "+f"(d[2]), "+f"(d[3])
                 : "r"(a[0]), "r"(a[1]), "r"(a[2]), "r"(a[3]), "r"(b[0]), "r"(b[1]));
}

// --------------------------------------------------------------------------
// Build A_hi/A_lo (bf16 split of P22) from low-rank factors. One pass.
// --------------------------------------------------------------------------
__global__ void build_split_kernel(const float* __restrict__ W,
                                   const float* __restrict__ U,
                                   const float* __restrict__ V,
                                   const float* __restrict__ Mv,
                                   const float* __restrict__ Z,
                                   const float* __restrict__ Cc,
                                   const float* __restrict__ Bm) {
    int i = blockIdx.y;
    int j = (blockIdx.x * blockDim.x + threadIdx.x) * 4;
    float cb = Cc[0] * Bm[0] + Cc[1] * Bm[1];
    float mi = Mv[i];
    float u0 = U[i * 4 + 0], u1 = U[i * 4 + 1], u2 = U[i * 4 + 2], u3 = U[i * 4 + 3];
    float4 w = *(const float4*)(W + (size_t)i * NN + j);
    const float* wp = &w.x;
    union { __nv_bfloat16 h[4]; uint2 u; } ph, pl;
#pragma unroll
    for (int jj = 0; jj < 4; ++jj) {
        int jc = j + jj;
        float4 vv = *(const float4*)(V + (size_t)jc * 4);
        float uv = u0 * vv.x + u1 * vv.y + u2 * vv.z + u3 * vv.w;
        float val = DTc * (wp[jj] + uv) + cb * mi * Z[jc];
        if (jc == i) val += 1.0f - DTc;
        __nv_bfloat16 hi = __float2bfloat16(val);
        ph.h[jj] = hi;
        pl.h[jj] = __float2bfloat16(val - __bfloat162float(hi));
    }
    *(uint2*)(g_Ahi + (size_t)i * NN + j) = ph.u;
    *(uint2*)(g_Alo + (size_t)i * NN + j) = pl.u;
}

// --------------------------------------------------------------------------
// Init: transpose h0 -> hT[0] and split to Bhi/Blo[0]
// --------------------------------------------------------------------------
__global__ void init_state_kernel(const float* __restrict__ h0) {
    int n = blockIdx.y;
    int m = blockIdx.x * 256 + threadIdx.x;
    float v = h0[(size_t)m * BB + n];
    size_t o = (size_t)n * NN + m;
    g_hT[0][o] = v;
    __nv_bfloat16 hi = __float2bfloat16(v);
    g_Bhi[0][o] = hi;
    g_Blo[0][o] = __float2bfloat16(v - __bfloat162float(hi));
}

__global__ void init_x_kernel(const float* __restrict__ x0, const float* __restrict__ x1) {
    int b = threadIdx.x;
    g_x[0][b] = x0[b];
    g_x[0][BB + b] = x1[b];
}

// --------------------------------------------------------------------------
// Transpose hT[p] ([BB][NN]) into traj h-block ([NN][BB])
// --------------------------------------------------------------------------
__global__ void transpose_out_kernel(float* __restrict__ dst, int p) {
    __shared__ float t[32][33];
    int mBase = blockIdx.x * 32, nBase = blockIdx.y * 32;
    int tx = threadIdx.x, ty = threadIdx.y;
    const float* __restrict__ hT = g_hT[p];
#pragma unroll
    for (int j = 0; j < 32; j += 8)
        t[ty + j][tx] = hT[(size_t)(nBase + ty + j) * NN + mBase + tx];
    __syncthreads();
#pragma unroll
    for (int j = 0; j < 32; j += 8)
        dst[(size_t)(mBase + ty + j) * BB + nBase + tx] = t[tx][ty + j];
}

// --------------------------------------------------------------------------
// Zh[n] = dot(Z, hT[p][n][:]) — one warp per n.
// --------------------------------------------------------------------------
__global__ void zh_kernel(int p, const float* __restrict__ Z) {
    int n = blockIdx.x * 8 + (threadIdx.x >> 5);
    int lane = threadIdx.x & 31;
    const float4* __restrict__ h4 = (const float4*)(g_hT[p] + (size_t)n * NN);
    const float4* __restrict__ z4 = (const float4*)Z;
    float s = 0.f;
#pragma unroll 4
    for (int i = lane; i < NN / 4; i += 32) {
        float4 a = h4[i], b = z4[i];
        s += a.x * b.x + a.y * b.y + a.z * b.z + a.w * b.w;
    }
#pragma unroll
    for (int o = 16; o; o >>= 1) s += __shfl_xor_sync(0xFFFFFFFFu, s, o);
    if (lane == 0) g_zh[n] = s;
}

// --------------------------------------------------------------------------
// x-update + con + traj x-rows.
// --------------------------------------------------------------------------
__global__ void xupdate_kernel(int p, const float* __restrict__ Amat,
                               const float* __restrict__ Bm,
                               float* __restrict__ traj_x,
                               float* __restrict__ con) {
    int b = threadIdx.x;
    float zh = g_zh[b];
    float x0 = g_x[p][b], x1 = g_x[p][BB + b];
    con[b] = Bm[1] * zh;
    traj_x[b] = x0;
    traj_x[BB + b] = x1;
    int q = p ^ 1;
    g_x[q][b] = Amat[0] * x0 + Amat[1] * x1 + Bm[0] * zh;
    g_x[q][BB + b] = Amat[2] * x0 + Amat[3] * x1 + Bm[1] * zh;
}

// --------------------------------------------------------------------------
// mma.sync GEMM step: hT[p^1] = P22 @ h (split-3 bf16) + DT*M*(C@A@x)
// grid (BB/BN=4, NN/BM=32), block 256, dyn smem SMEM_BYTES
// --------------------------------------------------------------------------
__device__ __forceinline__ void load_stage(uint32_t stg, int kt, int tid,
                                           int rowBase, int colBase,
                                           const __nv_bfloat16* Ah, const __nv_bfloat16* Al,
                                           const __nv_bfloat16* Bh, const __nv_bfloat16* Bl) {
#pragma unroll
    for (int i = 0; i < 8; ++i) {
        int ch = i * 256 + tid;          // 0..2047
        int tile = ch >> 9;              // 0..3
        int r = (ch >> 2) & 127;
        int c = ch & 3;
        const __nv_bfloat16* base = (tile == 0) ? Ah : (tile == 1) ? Al : (tile == 2) ? Bh : Bl;
        int rb = (tile < 2) ? rowBase : colBase;
        const char* src = (const char*)base + ((size_t)(rb + r) * NN + kt * BKt + c * 8) * 2;
        uint32_t dst = stg + tile * TILEB + r * ROWB + c * 16;
        cp16(dst, src);
    }
}

__global__ void __launch_bounds__(256, 1) gemm_step_kernel(
    int p, const float* __restrict__ Mv,
    const float* __restrict__ Cc, const float* __restrict__ Amat) {
    extern __shared__ __align__(128) char smem[];
    uint32_t sb = smem_u32(smem);
    int tid = threadIdx.x;
    int lane = tid & 31;
    int wid = tid >> 5;
    int rowBase = blockIdx.y * BM;
    int colBase = blockIdx.x * BN;

    const __nv_bfloat16* Ah = g_Ahi;
    const __nv_bfloat16* Al = g_Alo;
    const __nv_bfloat16* Bh = g_Bhi[p];
    const __nv_bfloat16* Bl = g_Blo[p];

    // Warp tiling: 2 (M) x 4 (N) warps; warp tile 64x32
    int mb = (wid >> 2) * 64;
    int nb = (wid & 3) * 32;
    uint32_t aRow = (uint32_t)(mb + (lane & 15));
    uint32_t aK = (uint32_t)((lane >> 4) * 8);
    uint32_t bRow = (uint32_t)(nb + (lane & 7));
    uint32_t bK = (uint32_t)(((lane >> 3) & 1) * 8);

    float acc[4][4][4];
#pragma unroll
    for (int mi = 0; mi < 4; ++mi)
#pragma unroll
        for (int ni = 0; ni < 4; ++ni)
#pragma unroll
            for (int k = 0; k < 4; ++k) acc[mi][ni][k] = 0.f;

    // prologue
#pragma unroll
    for (int s = 0; s < NSTG; ++s) {
        load_stage(sb + s * STAGEB, s, tid, rowBase, colBase, Ah, Al, Bh, Bl);
        asm volatile("cp.async.commit_group;" ::: "memory");
    }

    for (int kt = 0; kt < NKT; ++kt) {
        asm volatile("cp.async.wait_group 2;" ::: "memory");
        __syncthreads();
        uint32_t stg = sb + (uint32_t)(kt % NSTG) * STAGEB;
#pragma unroll
        for (int ks = 0; ks < BKt; ks += 16) {
            uint32_t ah[4][4], al2[4][4], bh2[4][2], bl2[4][2];
#pragma unroll
            for (int mi = 0; mi < 4; ++mi) {
                uint32_t a = stg + (aRow + mi * 16) * ROWB + (aK + ks) * 2;
                ldsm4(ah[mi], a);
                ldsm4(al2[mi], a + TILEB);
            }
#pragma unroll
            for (int ni = 0; ni < 4; ++ni) {
                uint32_t a = stg + 2 * TILEB + (bRow + ni * 8) * ROWB + (bK + ks) * 2;
                ldsm2(bh2[ni], a);
                ldsm2(bl2[ni], a + TILEB);
            }
#pragma unroll
            for (int mi = 0; mi < 4; ++mi)
#pragma unroll
                for (int ni = 0; ni < 4; ++ni) {
                    mma_bf16(acc[mi][ni], ah[mi], bh2[ni]);
                    mma_bf16(acc[mi][ni], ah[mi], bl2[ni]);
                    mma_bf16(acc[mi][ni], al2[mi], bh2[ni]);
                }
        }
        __syncthreads();
        if (kt + NSTG < NKT)
            load_stage(stg, kt + NSTG, tid, rowBase, colBase, Ah, Al, Bh, Bl);
        asm volatile("cp.async.commit_group;" ::: "memory");
    }

    // ---- Epilogue: frags -> smem [n][m], then fused coalesced writeout ----
    float* Cst = (float*)smem;           // [128][132]
#pragma unroll
    for (int mi = 0; mi < 4; ++mi)
#pragma unroll
        for (int ni = 0; ni < 4; ++ni) {
            int m = mb + mi * 16 + (lane >> 2);
            int n = nb + ni * 8 + (lane & 3) * 2;
            Cst[n * 132 + m] = acc[mi][ni][0];
            Cst[(n + 1) * 132 + m] = acc[mi][ni][1];
            Cst[n * 132 + m + 8] = acc[mi][ni][2];
            Cst[(n + 1) * 132 + m + 8] = acc[mi][ni][3];
        }
    __syncthreads();

    float CA0 = Cc[0] * Amat[0] + Cc[1] * Amat[2];
    float CA1 = Cc[0] * Amat[1] + Cc[1] * Amat[3];
    int n = tid >> 1;
    int m0 = (tid & 1) * 64;
    float e = CA0 * g_x[p][colBase + n] + CA1 * g_x[p][BB + colBase + n];
    float* __restrict__ hTn = g_hT[p ^ 1];
    __nv_bfloat16* __restrict__ Bhn = g_Bhi[p ^ 1];
    __nv_bfloat16* __restrict__ Bln = g_Blo[p ^ 1];
    size_t obase = (size_t)(colBase + n) * NN + rowBase;
#pragma unroll
    for (int q = 0; q < 16; ++q) {
        int m = m0 + q * 4;
        float4 c = *(float4*)&Cst[n * 132 + m];
        float4 mv4 = *(const float4*)&Mv[rowBase + m];
        float4 v;
        v.x = c.x + DTc * mv4.x * e;
        v.y = c.y + DTc * mv4.y * e;
        v.z = c.z + DTc * mv4.z * e;
        v.w = c.w + DTc * mv4.w * e;
        *(float4*)&hTn[obase + m] = v;
        union { __nv_bfloat16 h[4]; uint2 u; } ph, pl;
        const float* vp = &v.x;
#pragma unroll
        for (int j = 0; j < 4; ++j) {
            __nv_bfloat16 hi = __float2bfloat16(vp[j]);
            ph.h[j] = hi;
            pl.h[j] = __float2bfloat16(vp[j] - __bfloat162float(hi));
        }
        *(uint2*)&Bhn[obase + m] = ph.u;
        *(uint2*)&Bln[obase + m] = pl.u;
    }
}

// --------------------------------------------------------------------------
extern "C" void kernel_launch(void* const* d_in, const int* in_sizes, int n_in,
                              void* d_out, int out_size) {
    const float* x0 = (const float*)d_in[0];
    const float* x1 = (const float*)d_in[1];
    const float* h0 = (const float*)d_in[2];
    const float* A  = (const float*)d_in[3];
    const float* Bm = (const float*)d_in[4];
    const float* C  = (const float*)d_in[5];
    const float* Mv = (const float*)d_in[6];
    const float* Z  = (const float*)d_in[7];
    const float* U  = (const float*)d_in[8];
    const float* V  = (const float*)d_in[9];
    const float* W  = (const float*)d_in[10];

    long long per_step_full = (long long)BB * (NN + 2 + 1);
    int steps = (int)((long long)out_size / per_step_full);
    if ((long long)steps * per_step_full != (long long)out_size)
        steps = (int)((long long)out_size / ((long long)BB * (NN + 2)));

    float* out  = (float*)d_out;
    float* traj = out;
    float* con  = out + (size_t)steps * (NN + 2) * BB;

    cudaFuncSetAttribute(gemm_step_kernel,
                         cudaFuncAttributeMaxDynamicSharedMemorySize, SMEM_BYTES);

    build_split_kernel<<<dim3(NN / 4 / 256, NN), 256>>>(W, U, V, Mv, Z, C, Bm);
    init_state_kernel<<<dim3(NN / 256, BB), 256>>>(h0);
    init_x_kernel<<<1, BB>>>(x0, x1);

    for (int t = 0; t < steps; ++t) {
        int p = t & 1;
        float* traj_t = traj + (size_t)t * (NN + 2) * BB;
        transpose_out_kernel<<<dim3(NN / 32, BB / 32), dim3(32, 8)>>>(traj_t + 2 * BB, p);
        zh_kernel<<<BB / 8, 256>>>(p, Z);
        xupdate_kernel<<<1, BB>>>(p, A, Bm, traj_t, con + (size_t)t * BB);
        gemm_step_kernel<<<dim3(BB / BN, NN / BM), 256, SMEM_BYTES>>>(p, Mv, C, A);
    }
}

// round 4
// speedup vs baseline: 2.4639x; 1.0769x over previous
#include <cuda_runtime.h>
#include <cuda_bf16.h>
#include <cstdint>

#define NN 4096
#define BB 512
#define DTc 0.1f

// GEMM tiling (mma.sync bf16)
#define BM 128
#define BN 128
#define BKt 32
#define NKT (NN / BKt)        // 128 k-tile iterations
#define ROWB 80               // padded smem row bytes (64B data + 16B pad)
#define TILEB (128 * ROWB)    // 10240 bytes per operand tile
#define STAGEB (4 * TILEB)    // Ahi, Alo, Bhi, Blo
#define NSTG 3
#define SMEM_BYTES (NSTG * STAGEB)   // 122880  (>= 128*132*4 = 67584 epilogue reuse)

// --------------------------------------------------------------------------
// Device scratch (no allocation allowed)
// --------------------------------------------------------------------------
__device__ __align__(256) __nv_bfloat16 g_Ahi[(size_t)NN * NN];    // 32 MB
__device__ __align__(256) __nv_bfloat16 g_Alo[(size_t)NN * NN];    // 32 MB
__device__ __align__(256) __nv_bfloat16 g_Bhi[2][(size_t)BB * NN]; // 2x4 MB
__device__ __align__(256) __nv_bfloat16 g_Blo[2][(size_t)BB * NN]; // 2x4 MB
__device__ float g_x[2][2 * BB];
__device__ float g_zha[2][BB];     // ping-pong Z.h accumulators

// --------------------------------------------------------------------------
// Helpers
// --------------------------------------------------------------------------
__device__ __forceinline__ uint32_t smem_u32(const void* p) {
    return (uint32_t)__cvta_generic_to_shared((void*)p);
}

__device__ __forceinline__ void cp16(uint32_t dst, const void* src) {
    asm volatile("cp.async.cg.shared.global [%0], [%1], 16;" :: "r"(dst), "l"(src) : "memory");
}

__device__ __forceinline__ void ldsm4(uint32_t* r, uint32_t a) {
    asm volatile("ldmatrix.sync.aligned.m8n8.x4.shared.b16 {%0,%1,%2,%3}, [%4];"
                 : "=r"(r[0]), "=r"(r[1]), "=r"(r[2]), "=r"(r[3]) : "r"(a));
}

__device__ __forceinline__ void ldsm2(uint32_t* r, uint32_t a) {
    asm volatile("ldmatrix.sync.aligned.m8n8.x2.shared.b16 {%0,%1}, [%2];"
                 : "=r"(r[0]), "=r"(r[1]) : "r"(a));
}

__device__ __forceinline__ void mma_bf16(float* d, const uint32_t* a, const uint32_t* b) {
    asm volatile("mma.sync.aligned.m16n8k16.row.col.f32.bf16.bf16.f32 "
                 "{%0,%1,%2,%3}, {%4,%5,%6,%7}, {%8,%9}, {%0,%1,%2,%3};"
                 : "+f"(d[0]), "+f"(d[1]), "+f"(d[2]), "+f"(d[3])
                 : "r"(a[0]), "r"(a[1]), "r"(a[2]), "r"(a[3]), "r"(b[0]), "r"(b[1]));
}

// --------------------------------------------------------------------------
// Build A_hi/A_lo (bf16 split of P22); also zeroes the zh accumulators.
// --------------------------------------------------------------------------
__global__ void build_split_kernel(const float* __restrict__ W,
                                   const float* __restrict__ U,
                                   const float* __restrict__ V,
                                   const float* __restrict__ Mv,
                                   const float* __restrict__ Z,
                                   const float* __restrict__ Cc,
                                   const float* __restrict__ Bm) {
    if (blockIdx.x == 0 && blockIdx.y == 0) {
        int tIdx = threadIdx.x;
        g_zha[0][tIdx] = 0.f;       g_zha[1][tIdx] = 0.f;
        g_zha[0][tIdx + 256] = 0.f; g_zha[1][tIdx + 256] = 0.f;
    }
    int i = blockIdx.y;
    int j = (blockIdx.x * blockDim.x + threadIdx.x) * 4;
    float cb = Cc[0] * Bm[0] + Cc[1] * Bm[1];
    float mi = Mv[i];
    float u0 = U[i * 4 + 0], u1 = U[i * 4 + 1], u2 = U[i * 4 + 2], u3 = U[i * 4 + 3];
    float4 w = *(const float4*)(W + (size_t)i * NN + j);
    const float* wp = &w.x;
    union { __nv_bfloat16 h[4]; uint2 u; } ph, pl;
#pragma unroll
    for (int jj = 0; jj < 4; ++jj) {
        int jc = j + jj;
        float4 vv = *(const float4*)(V + (size_t)jc * 4);
        float uv = u0 * vv.x + u1 * vv.y + u2 * vv.z + u3 * vv.w;
        float val = DTc * (wp[jj] + uv) + cb * mi * Z[jc];
        if (jc == i) val += 1.0f - DTc;
        __nv_bfloat16 hi = __float2bfloat16(val);
        ph.h[jj] = hi;
        pl.h[jj] = __float2bfloat16(val - __bfloat162float(hi));
    }
    *(uint2*)(g_Ahi + (size_t)i * NN + j) = ph.u;
    *(uint2*)(g_Alo + (size_t)i * NN + j) = pl.u;
}

// --------------------------------------------------------------------------
// init: h0 -> traj_0 h-block (straight copy) + transposed bf16 split Bhi/Blo[0]
// grid (NN/32, BB/32), block (32,8)
// --------------------------------------------------------------------------
__global__ void init_state_kernel(const float* __restrict__ h0,
                                  float* __restrict__ traj0h) {
    __shared__ float t[32][33];
    int m0 = blockIdx.x * 32, b0 = blockIdx.y * 32;
    int tx = threadIdx.x, ty = threadIdx.y;
#pragma unroll
    for (int j = 0; j < 32; j += 8) {
        size_t a = (size_t)(m0 + ty + j) * BB + b0 + tx;
        float v = h0[a];
        traj0h[a] = v;
        t[ty + j][tx] = v;
    }
    __syncthreads();
#pragma unroll
    for (int j = 0; j < 32; j += 8) {
        float v = t[tx][ty + j];
        size_t o = (size_t)(b0 + ty + j) * NN + m0 + tx;
        __nv_bfloat16 hi = __float2bfloat16(v);
        g_Bhi[0][o] = hi;
        g_Blo[0][o] = __float2bfloat16(v - __bfloat162float(hi));
    }
}

// --------------------------------------------------------------------------
// zh for step 0: g_zha[0][b] += sum_m Z[m]*h0[m][b]. grid 32, block 512.
// --------------------------------------------------------------------------
__global__ void zh0_kernel(const float* __restrict__ h0, const float* __restrict__ Z) {
    int b = threadIdx.x;
    int m0 = blockIdx.x * 128;
    float s = 0.f;
#pragma unroll 4
    for (int m = m0; m < m0 + 128; ++m)
        s = fmaf(Z[m], h0[(size_t)m * BB + b], s);
    atomicAdd(&g_zha[0][b], s);
}

__global__ void init_x_kernel(const float* __restrict__ x0, const float* __restrict__ x1) {
    int b = threadIdx.x;
    g_x[0][b] = x0[b];
    g_x[0][BB + b] = x1[b];
}

// --------------------------------------------------------------------------
// Fused step kernel.
//   Block (0,0): x-update for step t (reads g_zha[p], zeroes it, writes con_t,
//                traj_t x-rows, g_x[p^1]).
//   All blocks (if do_mma): h_{t+1} = P22 @ h_t (split-3 bf16) + DT*M*(C A x_t);
//                writes traj_{t+1} h-block, Bhi/Blo[p^1], atomicAdds g_zha[p^1].
// grid (BB/BN=4, NN/BM=32), block 256, dyn smem SMEM_BYTES
// --------------------------------------------------------------------------
__device__ __forceinline__ void load_stage(uint32_t stg, int kt, int tid,
                                           int rowBase, int colBase,
                                           const __nv_bfloat16* Ah, const __nv_bfloat16* Al,
                                           const __nv_bfloat16* Bh, const __nv_bfloat16* Bl) {
#pragma unroll
    for (int i = 0; i < 8; ++i) {
        int ch = i * 256 + tid;          // 0..2047
        int tile = ch >> 9;              // 0..3
        int r = (ch >> 2) & 127;
        int c = ch & 3;
        const __nv_bfloat16* base = (tile == 0) ? Ah : (tile == 1) ? Al : (tile == 2) ? Bh : Bl;
        int rb = (tile < 2) ? rowBase : colBase;
        const char* src = (const char*)base + ((size_t)(rb + r) * NN + kt * BKt + c * 8) * 2;
        uint32_t dst = stg + tile * TILEB + r * ROWB + c * 16;
        cp16(dst, src);
    }
}

__global__ void __launch_bounds__(256, 1) gemm_step_kernel(
    int p, int do_mma,
    const float* __restrict__ Mv,
    const float* __restrict__ Cc, const float* __restrict__ Amat,
    const float* __restrict__ Bm, const float* __restrict__ Z,
    float* __restrict__ trajh_next,   // traj_{t+1} h-block [NN][BB]
    float* __restrict__ trajx_cur,    // traj_t x-rows [2][BB]
    float* __restrict__ con_cur) {    // con_t [BB]
    extern __shared__ __align__(128) char smem[];
    uint32_t sb = smem_u32(smem);
    int tid = threadIdx.x;
    int lane = tid & 31;
    int wid = tid >> 5;
    int rowBase = blockIdx.y * BM;
    int colBase = blockIdx.x * BN;
    int q2 = p ^ 1;

    // ---- fused x-update (step t), designated block only ----
    if (blockIdx.x == 0 && blockIdx.y == 0) {
#pragma unroll
        for (int it = 0; it < 2; ++it) {
            int b = tid + it * 256;
            float zh = g_zha[p][b];
            g_zha[p][b] = 0.f;
            float xv0 = g_x[p][b], xv1 = g_x[p][BB + b];
            con_cur[b] = Bm[1] * zh;
            trajx_cur[b] = xv0;
            trajx_cur[BB + b] = xv1;
            g_x[q2][b] = Amat[0] * xv0 + Amat[1] * xv1 + Bm[0] * zh;
            g_x[q2][BB + b] = Amat[2] * xv0 + Amat[3] * xv1 + Bm[1] * zh;
        }
    }
    if (!do_mma) return;

    const __nv_bfloat16* Ah = g_Ahi;
    const __nv_bfloat16* Al = g_Alo;
    const __nv_bfloat16* Bh = g_Bhi[p];
    const __nv_bfloat16* Bl = g_Blo[p];

    // Warp tiling: 2 (M) x 4 (N) warps; warp tile 64x32
    int mb = (wid >> 2) * 64;
    int nb = (wid & 3) * 32;
    uint32_t aRow = (uint32_t)(mb + (lane & 15));
    uint32_t aK = (uint32_t)((lane >> 4) * 8);
    uint32_t bRow = (uint32_t)(nb + (lane & 7));
    uint32_t bK = (uint32_t)(((lane >> 3) & 1) * 8);

    float acc[4][4][4];
#pragma unroll
    for (int mi = 0; mi < 4; ++mi)
#pragma unroll
        for (int ni = 0; ni < 4; ++ni)
#pragma unroll
            for (int k = 0; k < 4; ++k) acc[mi][ni][k] = 0.f;

#pragma unroll
    for (int s = 0; s < NSTG; ++s) {
        load_stage(sb + s * STAGEB, s, tid, rowBase, colBase, Ah, Al, Bh, Bl);
        asm volatile("cp.async.commit_group;" ::: "memory");
    }

    for (int kt = 0; kt < NKT; ++kt) {
        asm volatile("cp.async.wait_group 2;" ::: "memory");
        __syncthreads();
        uint32_t stg = sb + (uint32_t)(kt % NSTG) * STAGEB;
#pragma unroll
        for (int ks = 0; ks < BKt; ks += 16) {
            uint32_t ah[4][4], al2[4][4], bh2[4][2], bl2[4][2];
#pragma unroll
            for (int mi = 0; mi < 4; ++mi) {
                uint32_t a = stg + (aRow + mi * 16) * ROWB + (aK + ks) * 2;
                ldsm4(ah[mi], a);
                ldsm4(al2[mi], a + TILEB);
            }
#pragma unroll
            for (int ni = 0; ni < 4; ++ni) {
                uint32_t a = stg + 2 * TILEB + (bRow + ni * 8) * ROWB + (bK + ks) * 2;
                ldsm2(bh2[ni], a);
                ldsm2(bl2[ni], a + TILEB);
            }
#pragma unroll
            for (int mi = 0; mi < 4; ++mi)
#pragma unroll
                for (int ni = 0; ni < 4; ++ni) {
                    mma_bf16(acc[mi][ni], ah[mi], bh2[ni]);
                    mma_bf16(acc[mi][ni], ah[mi], bl2[ni]);
                    mma_bf16(acc[mi][ni], al2[mi], bh2[ni]);
                }
        }
        __syncthreads();
        if (kt + NSTG < NKT)
            load_stage(stg, kt + NSTG, tid, rowBase, colBase, Ah, Al, Bh, Bl);
        asm volatile("cp.async.commit_group;" ::: "memory");
    }
    __syncthreads();   // all smem reads done before Cst aliases the stages

    // ---- Epilogue pass 1: frags -> smem Cst [n][132] ----
    float* Cst = (float*)smem;
#pragma unroll
    for (int mi = 0; mi < 4; ++mi)
#pragma unroll
        for (int ni = 0; ni < 4; ++ni) {
            int m = mb + mi * 16 + (lane >> 2);
            int n = nb + ni * 8 + (lane & 3) * 2;
            Cst[n * 132 + m] = acc[mi][ni][0];
            Cst[(n + 1) * 132 + m] = acc[mi][ni][1];
            Cst[n * 132 + m + 8] = acc[mi][ni][2];
            Cst[(n + 1) * 132 + m + 8] = acc[mi][ni][3];
        }
    __syncthreads();

    // ---- Pass 2 (n-major): v = acc + DT*M*e; write Bhi/Blo, v->Cst, zh partial
    float CA0 = Cc[0] * Amat[0] + Cc[1] * Amat[2];
    float CA1 = Cc[0] * Amat[1] + Cc[1] * Amat[3];
    {
        int n = tid >> 1;
        int m0 = (tid & 1) * 64;
        float e = CA0 * g_x[p][colBase + n] + CA1 * g_x[p][BB + colBase + n];
        __nv_bfloat16* __restrict__ Bhn = g_Bhi[q2];
        __nv_bfloat16* __restrict__ Bln = g_Blo[q2];
        size_t obase = (size_t)(colBase + n) * NN + rowBase;
        float zp = 0.f;
#pragma unroll
        for (int q = 0; q < 16; ++q) {
            int m = m0 + q * 4;
            float4 c = *(float4*)&Cst[n * 132 + m];
            float4 mv4 = *(const float4*)&Mv[rowBase + m];
            float4 z4 = *(const float4*)&Z[rowBase + m];
            float4 v;
            v.x = c.x + DTc * mv4.x * e;
            v.y = c.y + DTc * mv4.y * e;
            v.z = c.z + DTc * mv4.z * e;
            v.w = c.w + DTc * mv4.w * e;
            *(float4*)&Cst[n * 132 + m] = v;
            zp += z4.x * v.x + z4.y * v.y + z4.z * v.z + z4.w * v.w;
            union { __nv_bfloat16 h[4]; uint2 u; } ph, pl;
            const float* vp = &v.x;
#pragma unroll
            for (int j = 0; j < 4; ++j) {
                __nv_bfloat16 hi = __float2bfloat16(vp[j]);
                ph.h[j] = hi;
                pl.h[j] = __float2bfloat16(vp[j] - __bfloat162float(hi));
            }
            *(uint2*)&Bhn[obase + m] = ph.u;
            *(uint2*)&Bln[obase + m] = pl.u;
        }
        // combine the two m-halves (lanes differ only in bit 0)
        zp += __shfl_xor_sync(0xFFFFFFFFu, zp, 1);
        if ((tid & 1) == 0)
            atomicAdd(&g_zha[q2][colBase + n], zp);
    }
    __syncthreads();

    // ---- Pass 3 (m-major): traj_{t+1} h-block [m][b], b contiguous ----
    {
        int m = tid >> 1;
        int n0 = (tid & 1) * 64;
        size_t tb = (size_t)(rowBase + m) * BB + colBase + n0;
#pragma unroll
        for (int q = 0; q < 16; ++q) {
            float4 v;
            v.x = Cst[(n0 + q * 4 + 0) * 132 + m];
            v.y = Cst[(n0 + q * 4 + 1) * 132 + m];
            v.z = Cst[(n0 + q * 4 + 2) * 132 + m];
            v.w = Cst[(n0 + q * 4 + 3) * 132 + m];
            *(float4*)&trajh_next[tb + q * 4] = v;
        }
    }
}

// --------------------------------------------------------------------------
extern "C" void kernel_launch(void* const* d_in, const int* in_sizes, int n_in,
                              void* d_out, int out_size) {
    const float* x0 = (const float*)d_in[0];
    const float* x1 = (const float*)d_in[1];
    const float* h0 = (const float*)d_in[2];
    const float* A  = (const float*)d_in[3];
    const float* Bm = (const float*)d_in[4];
    const float* C  = (const float*)d_in[5];
    const float* Mv = (const float*)d_in[6];
    const float* Z  = (const float*)d_in[7];
    const float* U  = (const float*)d_in[8];
    const float* V  = (const float*)d_in[9];
    const float* W  = (const float*)d_in[10];

    long long per_step_full = (long long)BB * (NN + 2 + 1);
    int steps = (int)((long long)out_size / per_step_full);
    if ((long long)steps * per_step_full != (long long)out_size)
        steps = (int)((long long)out_size / ((long long)BB * (NN + 2)));

    float* out  = (float*)d_out;
    float* traj = out;
    float* con  = out + (size_t)steps * (NN + 2) * BB;

    cudaFuncSetAttribute(gemm_step_kernel,
                         cudaFuncAttributeMaxDynamicSharedMemorySize, SMEM_BYTES);

    build_split_kernel<<<dim3(NN / 4 / 256, NN), 256>>>(W, U, V, Mv, Z, C, Bm);
    init_state_kernel<<<dim3(NN / 32, BB / 32), dim3(32, 8)>>>(h0, traj + 2 * BB);
    zh0_kernel<<<32, 512>>>(h0, Z);
    init_x_kernel<<<1, BB>>>(x0, x1);

    for (int t = 0; t < steps; ++t) {
        int p = t & 1;
        int do_mma = (t < steps - 1);
        float* traj_t = traj + (size_t)t * (NN + 2) * BB;
        float* trajh_next = traj + (size_t)(t + 1) * (NN + 2) * BB + 2 * BB;
        if (!do_mma) trajh_next = traj_t + 2 * BB;   // unused, keep in-bounds
        gemm_step_kernel<<<dim3(BB / BN, NN / BM), 256, SMEM_BYTES>>>(
            p, do_mma, Mv, C, A, Bm, Z,
            trajh_next, traj_t, con + (size_t)t * BB);
    }
}